// round 16
// baseline (speedup 1.0000x reference)
#include <cuda_runtime.h>
#include <cuda_fp16.h>
#include <math.h>
#include <stdint.h>

#define Nn   4096
#define Bb   2048
#define DIM  128
#define NT   32
#define NTILES 528
#define GRID2 132                       // simgen: 132 CTAs x exactly 4 tiles
#define EGRID 296                       // epiflat: persistent, ~2 CTAs/SM
#define EPSV 1e-8f
#define INV_T 14.285714285714285714f   // 1/0.07
#define LOG2E 1.44269504088896340736f

// ---------------- static device scratch ----------------
__device__ __half          g_zf[Nn * DIM];                 // 1 MB fp16 normalized z
__device__ float           g_simu[(size_t)NTILES * 16384]; // 34.6 MB upper-tri tiles
__device__ float           g_pdr[3][Nn][NT];               // row-side partials [k][i][slot]
__device__ float           g_pdc[3][Nn][NT];               // col-side partials [k][i][slot]
__device__ float           g_part[NT];                     // per-block-row loss partials
__device__ int             g_rowdone[NT];                  // tiles completed per block-row
__device__ float           g_inv_dymax;
__device__ unsigned        g_min_key;
__device__ int             g_tick;
__device__ int             g_done;

// panel layout in dynamic smem (fp16, 128 rows x 136 stride = 272 B/row)
#define PSTRIDE_B 272
#define OFF_A    0
#define OFF_B0   34816
#define OFF_B1   69632
#define PANEL_BYTES 104448

__device__ __forceinline__ unsigned fflip(float f) {
    unsigned u = __float_as_uint(f);
    return (u & 0x80000000u) ? ~u : (u | 0x80000000u);
}
__device__ __forceinline__ float funflip(unsigned k) {
    return __uint_as_float((k & 0x80000000u) ? (k & 0x7FFFFFFFu) : ~k);
}
__device__ __forceinline__ uint32_t smem_u32(const void* p) {
    uint32_t a;
    asm("{ .reg .u64 t; cvta.to.shared.u64 t, %1; cvt.u32.u64 %0, t; }" : "=r"(a) : "l"(p));
    return a;
}
__device__ __forceinline__ void cp16(uint32_t s, const void* g) {
    asm volatile("cp.async.cg.shared.global [%0], [%1], 16;" :: "r"(s), "l"(g));
}
__device__ __forceinline__ void cp_commit() {
    asm volatile("cp.async.commit_group;");
}
template <int N> __device__ __forceinline__ void cp_wait() {
    asm volatile("cp.async.wait_group %0;" :: "n"(N));
}
__device__ __forceinline__ void ldsm4(uint32_t& r0, uint32_t& r1, uint32_t& r2, uint32_t& r3, uint32_t a) {
    asm volatile("ldmatrix.sync.aligned.m8n8.x4.shared.b16 {%0,%1,%2,%3}, [%4];"
                 : "=r"(r0), "=r"(r1), "=r"(r2), "=r"(r3) : "r"(a));
}
__device__ __forceinline__ void mma16816(float* c, const uint32_t* a, const uint32_t* b) {
    asm volatile("mma.sync.aligned.m16n8k16.row.col.f32.f16.f16.f32 "
                 "{%0,%1,%2,%3},{%4,%5,%6,%7},{%8,%9},{%0,%1,%2,%3};"
                 : "+f"(c[0]), "+f"(c[1]), "+f"(c[2]), "+f"(c[3])
                 : "r"(a[0]), "r"(a[1]), "r"(a[2]), "r"(a[3]), "r"(b[0]), "r"(b[1]));
}

// ---------------- kernel 1: normalize -> fp16 + labels/init -----------------
__global__ void prep_kernel(const float* __restrict__ feats,
                            const float* __restrict__ labels) {
    if (blockIdx.x == 512) {
        __shared__ float smn[8], smx[8];
        int tid = threadIdx.x;
        float mn = 1e30f, mx = -1e30f;
        for (int i = tid; i < Bb; i += 256) {
            float v = labels[i];
            mn = fminf(mn, v); mx = fmaxf(mx, v);
        }
        #pragma unroll
        for (int off = 16; off; off >>= 1) {
            mn = fminf(mn, __shfl_xor_sync(0xffffffffu, mn, off));
            mx = fmaxf(mx, __shfl_xor_sync(0xffffffffu, mx, off));
        }
        int lane = tid & 31, w = tid >> 5;
        if (lane == 0) { smn[w] = mn; smx[w] = mx; }
        __syncthreads();
        if (tid < NT) g_rowdone[tid] = 0;
        if (tid == 0) {
            float a = smn[0], b = smx[0];
            for (int i = 1; i < 8; i++) { a = fminf(a, smn[i]); b = fmaxf(b, smx[i]); }
            g_inv_dymax = 1.0f / ((b - a) + EPSV);
            g_min_key   = 0xFFFFFFFFu;
            g_tick      = 0;
            g_done      = 0;
        }
        return;
    }
    int gw   = (blockIdx.x * blockDim.x + threadIdx.x) >> 5;
    int lane = threadIdx.x & 31;
    int b = gw & (Bb - 1);
    int v = gw >> 11;
    const float* src = feats + ((size_t)b * 2 + v) * DIM;
    float4 x = *(const float4*)(src + lane * 4);
    float s = x.x * x.x + x.y * x.y + x.z * x.z + x.w * x.w;
    #pragma unroll
    for (int off = 16; off; off >>= 1) s += __shfl_xor_sync(0xffffffffu, s, off);
    float inv = 1.0f / fmaxf(sqrtf(s), 1e-12f);
    __half2 h01 = __floats2half2_rn(x.x * inv, x.y * inv);
    __half2 h23 = __floats2half2_rn(x.z * inv, x.w * inv);
    size_t base = (size_t)gw * DIM + lane * 4;
    *(__half2*)(g_zf + base)     = h01;
    *(__half2*)(g_zf + base + 2) = h23;
}

// ---- cp.async panel loader (one 128-row fp16 block), 512 threads ----
__device__ __forceinline__ void load_panel(uint32_t sb, uint32_t off,
                                           int blk, int tid) {
    #pragma unroll
    for (int c = tid; c < 2048; c += 512) {
        int row = c >> 4, ch = c & 15;
        uint32_t so = (uint32_t)row * PSTRIDE_B + ch * 16;
        size_t go = (size_t)(blk * 128 + row) * DIM + ch * 8;
        cp16(sb + off + so, g_zf + go);
    }
}

// ---- single-pass fp16 MMA (16 warps, 32x32 outputs each) ----
__device__ __forceinline__ void tile_mma(uint32_t sb, uint32_t offB,
                                         int wm, int wn, int lane, float c[2][4][4]) {
    #pragma unroll
    for (int im = 0; im < 2; im++)
        #pragma unroll
        for (int in = 0; in < 4; in++)
            #pragma unroll
            for (int r = 0; r < 4; r++) c[im][in][r] = 0.0f;

    int a_row  = lane & 15;
    int a_koff = (lane >> 4) * 8;
    int b_row  = ((lane >> 4) & 1) * 8 + (lane & 7);
    int b_koff = ((lane >> 3) & 1) * 8;

    #pragma unroll
    for (int kc = 0; kc < 8; kc++) {
        uint32_t ah[2][4], bh[4][2];
        #pragma unroll
        for (int im = 0; im < 2; im++) {
            uint32_t off = (uint32_t)(wm * 32 + im * 16 + a_row) * PSTRIDE_B
                         + (kc * 16 + a_koff) * 2;
            ldsm4(ah[im][0], ah[im][1], ah[im][2], ah[im][3], sb + OFF_A + off);
        }
        #pragma unroll
        for (int p = 0; p < 2; p++) {
            uint32_t off = (uint32_t)(wn * 32 + p * 16 + b_row) * PSTRIDE_B
                         + (kc * 16 + b_koff) * 2;
            ldsm4(bh[2*p][0], bh[2*p][1], bh[2*p+1][0], bh[2*p+1][1], sb + offB + off);
        }
        #pragma unroll
        for (int im = 0; im < 2; im++)
            #pragma unroll
            for (int in = 0; in < 4; in++)
                mma16816(c[im][in], ah[im], bh[in]);
    }
}

// ---------------- kernel 2: persistent pipelined GEMM (132 x 4 tiles) -------
__global__ void __launch_bounds__(512, 1) simgen_kernel() {
    extern __shared__ char sm[];
    __shared__ float wmin[16];
    uint32_t sb = smem_u32(sm);
    int tid = threadIdx.x, wid = tid >> 5, lane = tid & 31;
    int wm = wid & 3, wn = wid >> 2;
    int tr = lane >> 2, tq = (lane & 3) * 2;

    int ts = blockIdx.x * 4;
    int te = ts + 4;

    int by = 0, off = 0;
    while (ts >= off + (NT - by)) { off += (NT - by); by++; }
    int bx = by + (ts - off);

    float mymin = 1e30f;
    int t = ts;
    while (t < te) {
        int nb = NT - bx;
        if (nb > te - t) nb = te - t;

        load_panel(sb, OFF_A, by, tid);
        load_panel(sb, OFF_B0, bx, tid);
        cp_commit();

        for (int j = 0; j < nb; j++) {
            uint32_t bOf = (j & 1) ? OFF_B1 : OFF_B0;
            if (j + 1 < nb) {
                load_panel(sb, (j & 1) ? OFF_B0 : OFF_B1, bx + j + 1, tid);
                cp_commit();
                cp_wait<1>();
            } else {
                cp_wait<0>();
            }
            __syncthreads();

            float c[2][4][4];
            tile_mma(sb, bOf, wm, wn, lane, c);

            float* dst = g_simu + (size_t)(t + j) * 16384;
            #pragma unroll
            for (int im = 0; im < 2; im++)
                #pragma unroll
                for (int in = 0; in < 4; in++) {
                    int rl = wm * 32 + im * 16 + tr;
                    int cl = wn * 32 + in * 8 + tq;
                    float2 v0 = make_float2(c[im][in][0], c[im][in][1]);
                    float2 v1 = make_float2(c[im][in][2], c[im][in][3]);
                    *(float2*)(dst + rl * 128 + cl)       = v0;
                    *(float2*)(dst + (rl + 8) * 128 + cl) = v1;
                    mymin = fminf(mymin, fminf(fminf(v0.x, v0.y), fminf(v1.x, v1.y)));
                }
            __syncthreads();
        }
        t += nb;
        bx += nb;
        if (bx >= NT) { by++; bx = by; }
    }

    #pragma unroll
    for (int o = 16; o; o >>= 1) mymin = fminf(mymin, __shfl_xor_sync(0xffffffffu, mymin, o));
    if (lane == 0) wmin[wid] = mymin;
    __syncthreads();
    if (tid == 0) {
        float m = wmin[0];
        #pragma unroll
        for (int w = 1; w < 16; w++) m = fminf(m, wmin[w]);
        atomicMin(&g_min_key, fflip(m));
    }
}

// ---- block-row final reduction (runs inside epiflat when row-block ready) --
// 512 threads: warp w handles rows p*128 + w*8 .. +7; deterministic fixed trees.
__device__ __forceinline__ void reduce_blockrow(int p, int tid, int w, int l,
                                                float* wsum, float* out) {
    float acc = 0.0f;
    #pragma unroll
    for (int k = 0; k < 8; k++) {
        int i = p * 128 + w * 8 + k;
        float d = 0.0f, a = 0.0f, b = 0.0f;
        if (l >= p) {                  // row-side: tiles (p, l)
            d = g_pdr[0][i][l];
            a = g_pdr[1][i][l];
            b = g_pdr[2][i][l];
        }
        if (l <= p) {                  // col-side: tiles (l, p); diag slot = 0
            d += g_pdc[0][i][l];
            a += g_pdc[1][i][l];
            b += g_pdc[2][i][l];
        }
        #pragma unroll
        for (int o = 16; o; o >>= 1) {
            d += __shfl_xor_sync(0xffffffffu, d, o);
            a += __shfl_xor_sync(0xffffffffu, a, o);
            b += __shfl_xor_sync(0xffffffffu, b, o);
        }
        if (l == 0) {
            b *= INV_T;
            float L = logf(d + EPSV);
            acc += (b - a * L) / (a + EPSV);
        }
    }
    if (l == 0) wsum[w] = acc;
    __syncthreads();
    if (tid == 0) {
        float s = 0.0f;
        #pragma unroll
        for (int x = 0; x < 16; x++) s += wsum[x];
        g_part[p] = s;
        __threadfence();
        int old = atomicAdd(&g_done, 1);
        if (old == NT - 1) {           // all 32 block-rows reduced
            float tot = 0.0f;
            #pragma unroll
            for (int x = 0; x < NT; x++) tot += *(volatile float*)&g_part[x];
            out[0] = -(tot / (float)Nn);
        }
    }
    __syncthreads();
}

// ---------------- kernel 3: persistent epilogue + fused final reduce --------
__global__ void __launch_bounds__(512, 2) epiflat_kernel(const float* __restrict__ labels,
                                                         float* __restrict__ out) {
    __shared__ float yr[128], yc[128];
    __shared__ float rowacc[3][4][128];
    __shared__ float colacc[16][3][128];
    __shared__ int s_t;
    __shared__ int s_r0, s_r1;
    int tid = threadIdx.x, w = tid >> 5, l = tid & 31;

    float inv_dz = 1.0f / ((1.0f - funflip(g_min_key)) + EPSV);
    float inv_dy = g_inv_dymax;
    const float K1 = INV_T * LOG2E;
    const float K2 = -2.0f * LOG2E;

    while (true) {
        if (tid == 0) s_t = atomicAdd(&g_tick, 1);
        __syncthreads();
        int t = s_t;
        if (t >= NTILES) return;

        int by = 0, off = 0;
        while (t >= off + (NT - by)) { off += (NT - by); by++; }
        int bx = by + (t - off);
        bool diag = (by == bx);

        for (int i = tid; i < 128; i += 512) {
            yr[i] = labels[(by * 128 + i) & (Bb - 1)];
            yc[i] = labels[(bx * 128 + i) & (Bb - 1)];
        }
        __syncthreads();

        const float4* tp = (const float4*)(g_simu + (size_t)t * 16384);
        float yj[4];
        #pragma unroll
        for (int e = 0; e < 4; e++) yj[e] = yc[4 * l + e];

        float cd[4] = {0,0,0,0}, c1v[4] = {0,0,0,0}, c2v[4] = {0,0,0,0};

        #pragma unroll
        for (int it = 0; it < 8; it++) {
            int row = it * 16 + w;
            float4 s4 = tp[row * 32 + l];
            float se[4] = {s4.x, s4.y, s4.z, s4.w};
            float yi = yr[row];
            float rd = 0.0f, r1 = 0.0f, r2 = 0.0f;

            if (!diag) {
                #pragma unroll
                for (int e = 0; e < 4; e++) {
                    float s   = se[e];
                    float es  = exp2f(s * K1);
                    float dy  = yi - yj[e];
                    float wk  = exp2f(dy * (dy * K2));
                    float u   = fmaf(-s, inv_dz, fmaf(-fabsf(dy), inv_dy, inv_dz));
                    float wh  = fmaf(wk, u, 1.0f + fmaxf(-u, 0.0f));
                    float wh2 = wh * wh;
                    rd += es; r1 += wh; r2 = fmaf(wh2, s, r2);
                    cd[e] += es; c1v[e] += wh; c2v[e] = fmaf(wh2, s, c2v[e]);
                }
            } else {
                #pragma unroll
                for (int e = 0; e < 4; e++) {
                    float s   = se[e];
                    float es  = exp2f(s * K1);
                    float dy  = yi - yj[e];
                    float wk  = exp2f(dy * (dy * K2));
                    float u   = fmaf(-s, inv_dz, fmaf(-fabsf(dy), inv_dy, inv_dz));
                    float wh  = fmaf(wk, u, 1.0f + fmaxf(-u, 0.0f));
                    if (row == 4 * l + e) { es = 0.0f; wh = 0.0f; }
                    float wh2 = wh * wh;
                    rd += es; r1 += wh; r2 = fmaf(wh2, s, r2);
                    cd[e] += es; c1v[e] += wh; c2v[e] = fmaf(wh2, s, c2v[e]);
                }
            }

            #pragma unroll
            for (int o = 1; o <= 4; o <<= 1) {
                rd += __shfl_xor_sync(0xffffffffu, rd, o);
                r1 += __shfl_xor_sync(0xffffffffu, r1, o);
                r2 += __shfl_xor_sync(0xffffffffu, r2, o);
            }
            if ((l & 7) == 0) {
                int g = l >> 3;
                rowacc[0][g][row] = rd;
                rowacc[1][g][row] = r1;
                rowacc[2][g][row] = r2;
            }
        }

        #pragma unroll
        for (int e = 0; e < 4; e++) {
            colacc[w][0][4 * l + e] = cd[e];
            colacc[w][1][4 * l + e] = c1v[e];
            colacc[w][2][4 * l + e] = c2v[e];
            cd[e] = 0.0f; c1v[e] = 0.0f; c2v[e] = 0.0f;
        }
        __syncthreads();

        if (tid < 128) {
            int row = tid, ig = by * 128 + row;
            #pragma unroll
            for (int k = 0; k < 3; k++)
                g_pdr[k][ig][bx] = (rowacc[k][0][row] + rowacc[k][1][row])
                                 + (rowacc[k][2][row] + rowacc[k][3][row]);
        } else if (tid < 256) {
            int col = tid - 128, jg = bx * 128 + col;
            #pragma unroll
            for (int k = 0; k < 3; k++) {
                float v = 0.0f;
                #pragma unroll
                for (int ww = 0; ww < 16; ww++) v += colacc[ww][k][col];
                g_pdc[k][jg][by] = diag ? 0.0f : v;
            }
        }
        __syncthreads();                   // partial writes done CTA-wide

        // ---- block-row completion tracking (release: fence then atomics) ----
        if (tid == 0) {
            __threadfence();
            s_r0 = -1; s_r1 = -1;
            int c0 = atomicAdd(&g_rowdone[by], 1) + 1;
            if (c0 == NT) s_r0 = by;
            if (bx != by) {
                int c1 = atomicAdd(&g_rowdone[bx], 1) + 1;
                if (c1 == NT) s_r1 = bx;
            }
        }
        __syncthreads();
        if (s_r0 >= 0 || s_r1 >= 0) {
            __threadfence();               // acquire side
            if (s_r0 >= 0) reduce_blockrow(s_r0, tid, w, l, yr, out);  // reuse yr smem
            if (s_r1 >= 0) reduce_blockrow(s_r1, tid, w, l, yr, out);
        }
        __syncthreads();
    }
}

// ---------------- launch ----------------
extern "C" void kernel_launch(void* const* d_in, const int* in_sizes, int n_in,
                              void* d_out, int out_size) {
    const float* feats  = (const float*)d_in[0];
    const float* labels = (const float*)d_in[1];
    float* out = (float*)d_out;

    cudaFuncSetAttribute(simgen_kernel, cudaFuncAttributeMaxDynamicSharedMemorySize, PANEL_BYTES);

    prep_kernel<<<513, 256>>>(feats, labels);
    simgen_kernel<<<GRID2, 512, PANEL_BYTES>>>();
    epiflat_kernel<<<EGRID, 512>>>(labels, out);
}

// round 17
// speedup vs baseline: 1.2469x; 1.2469x over previous
#include <cuda_runtime.h>
#include <cuda_fp16.h>
#include <math.h>
#include <stdint.h>

#define Nn   4096
#define Bb   2048
#define DIM  128
#define NT   32
#define NTILES 528
#define GRID2 132                       // simgen: 132 CTAs x exactly 4 tiles
#define EGRID 296                       // epiflat: persistent, ~2 CTAs/SM
#define RGRID 128                       // rowfinal: 128 CTAs x 32 warps (warp/row)
#define EPSV 1e-8f
#define INV_T 14.285714285714285714f   // 1/0.07
#define LOG2E 1.44269504088896340736f

// ---------------- static device scratch ----------------
__device__ __half          g_zf[Nn * DIM];                 // 1 MB fp16 normalized z
__device__ float           g_simu[(size_t)NTILES * 16384]; // 34.6 MB upper-tri tiles
__device__ float           g_pdr[3][Nn][NT];               // row-side partials [k][i][slot]
__device__ float           g_pdc[3][Nn][NT];               // col-side partials [k][i][slot]
__device__ float           g_part[RGRID];
__device__ float           g_inv_dymax;
__device__ unsigned        g_min_key;
__device__ int             g_tick;
__device__ int             g_done;
__device__ int             g_arrive;   // monotonic ticket barrier (zero-init, graph-safe)

// panel layout in dynamic smem (fp16, 128 rows x 136 stride = 272 B/row)
#define PSTRIDE_B 272
#define OFF_A    0
#define OFF_B0   34816
#define OFF_B1   69632
#define PANEL_BYTES 104448

__device__ __forceinline__ unsigned fflip(float f) {
    unsigned u = __float_as_uint(f);
    return (u & 0x80000000u) ? ~u : (u | 0x80000000u);
}
__device__ __forceinline__ float funflip(unsigned k) {
    return __uint_as_float((k & 0x80000000u) ? (k & 0x7FFFFFFFu) : ~k);
}
__device__ __forceinline__ uint32_t smem_u32(const void* p) {
    uint32_t a;
    asm("{ .reg .u64 t; cvta.to.shared.u64 t, %1; cvt.u32.u64 %0, t; }" : "=r"(a) : "l"(p));
    return a;
}
__device__ __forceinline__ void cp16(uint32_t s, const void* g) {
    asm volatile("cp.async.cg.shared.global [%0], [%1], 16;" :: "r"(s), "l"(g));
}
__device__ __forceinline__ void cp_commit() {
    asm volatile("cp.async.commit_group;");
}
template <int N> __device__ __forceinline__ void cp_wait() {
    asm volatile("cp.async.wait_group %0;" :: "n"(N));
}
__device__ __forceinline__ void ldsm4(uint32_t& r0, uint32_t& r1, uint32_t& r2, uint32_t& r3, uint32_t a) {
    asm volatile("ldmatrix.sync.aligned.m8n8.x4.shared.b16 {%0,%1,%2,%3}, [%4];"
                 : "=r"(r0), "=r"(r1), "=r"(r2), "=r"(r3) : "r"(a));
}
__device__ __forceinline__ void mma16816(float* c, const uint32_t* a, const uint32_t* b) {
    asm volatile("mma.sync.aligned.m16n8k16.row.col.f32.f16.f16.f32 "
                 "{%0,%1,%2,%3},{%4,%5,%6,%7},{%8,%9},{%0,%1,%2,%3};"
                 : "+f"(c[0]), "+f"(c[1]), "+f"(c[2]), "+f"(c[3])
                 : "r"(a[0]), "r"(a[1]), "r"(a[2]), "r"(a[3]), "r"(b[0]), "r"(b[1]));
}

// ---- cp.async panel loader (one 128-row fp16 block), 512 threads ----
__device__ __forceinline__ void load_panel(uint32_t sb, uint32_t off,
                                           int blk, int tid) {
    #pragma unroll
    for (int c = tid; c < 2048; c += 512) {
        int row = c >> 4, ch = c & 15;
        uint32_t so = (uint32_t)row * PSTRIDE_B + ch * 16;
        size_t go = (size_t)(blk * 128 + row) * DIM + ch * 8;
        cp16(sb + off + so, g_zf + go);
    }
}

// ---- single-pass fp16 MMA (16 warps, 32x32 outputs each) ----
__device__ __forceinline__ void tile_mma(uint32_t sb, uint32_t offB,
                                         int wm, int wn, int lane, float c[2][4][4]) {
    #pragma unroll
    for (int im = 0; im < 2; im++)
        #pragma unroll
        for (int in = 0; in < 4; in++)
            #pragma unroll
            for (int r = 0; r < 4; r++) c[im][in][r] = 0.0f;

    int a_row  = lane & 15;
    int a_koff = (lane >> 4) * 8;
    int b_row  = ((lane >> 4) & 1) * 8 + (lane & 7);
    int b_koff = ((lane >> 3) & 1) * 8;

    #pragma unroll
    for (int kc = 0; kc < 8; kc++) {
        uint32_t ah[2][4], bh[4][2];
        #pragma unroll
        for (int im = 0; im < 2; im++) {
            uint32_t off = (uint32_t)(wm * 32 + im * 16 + a_row) * PSTRIDE_B
                         + (kc * 16 + a_koff) * 2;
            ldsm4(ah[im][0], ah[im][1], ah[im][2], ah[im][3], sb + OFF_A + off);
        }
        #pragma unroll
        for (int p = 0; p < 2; p++) {
            uint32_t off = (uint32_t)(wn * 32 + p * 16 + b_row) * PSTRIDE_B
                         + (kc * 16 + b_koff) * 2;
            ldsm4(bh[2*p][0], bh[2*p][1], bh[2*p+1][0], bh[2*p+1][1], sb + offB + off);
        }
        #pragma unroll
        for (int im = 0; im < 2; im++)
            #pragma unroll
            for (int in = 0; in < 4; in++)
                mma16816(c[im][in], ah[im], bh[in]);
    }
}

// ---------------- kernel 1: fused prep + persistent pipelined GEMM ----------
// Phase 0: normalize/fp16-encode rows (all CTAs) + labels/init (CTA 0).
// Ticket barrier (all 132 CTAs co-resident). Phase 1: GEMM on 4 tiles each.
__global__ void __launch_bounds__(512, 1) simgen_kernel(const float* __restrict__ feats,
                                                        const float* __restrict__ labels) {
    extern __shared__ char sm[];
    __shared__ float wmin[16];
    uint32_t sb = smem_u32(sm);
    int tid = threadIdx.x, wid = tid >> 5, lane = tid & 31;
    int wm = wid & 3, wn = wid >> 2;
    int tr = lane >> 2, tq = (lane & 3) * 2;

    // ---------------- phase 0: prep ----------------
    for (int gw = blockIdx.x * 16 + wid; gw < Nn; gw += GRID2 * 16) {
        int b = gw & (Bb - 1);
        int v = gw >> 11;
        const float* src = feats + ((size_t)b * 2 + v) * DIM;
        float4 x = *(const float4*)(src + lane * 4);
        float s = x.x * x.x + x.y * x.y + x.z * x.z + x.w * x.w;
        #pragma unroll
        for (int off = 16; off; off >>= 1) s += __shfl_xor_sync(0xffffffffu, s, off);
        float inv = 1.0f / fmaxf(sqrtf(s), 1e-12f);
        __half2 h01 = __floats2half2_rn(x.x * inv, x.y * inv);
        __half2 h23 = __floats2half2_rn(x.z * inv, x.w * inv);
        size_t base = (size_t)gw * DIM + lane * 4;
        *(__half2*)(g_zf + base)     = h01;
        *(__half2*)(g_zf + base + 2) = h23;
    }
    if (blockIdx.x == 0) {
        // labels min/max + global init
        float mn = 1e30f, mx = -1e30f;
        for (int i = tid; i < Bb; i += 512) {
            float v = labels[i];
            mn = fminf(mn, v); mx = fmaxf(mx, v);
        }
        #pragma unroll
        for (int off = 16; off; off >>= 1) {
            mn = fminf(mn, __shfl_xor_sync(0xffffffffu, mn, off));
            mx = fmaxf(mx, __shfl_xor_sync(0xffffffffu, mx, off));
        }
        __shared__ float smn[16], smx[16];
        if (lane == 0) { smn[wid] = mn; smx[wid] = mx; }
        __syncthreads();
        if (tid == 0) {
            float a = smn[0], b = smx[0];
            #pragma unroll
            for (int i = 1; i < 16; i++) { a = fminf(a, smn[i]); b = fmaxf(b, smx[i]); }
            g_inv_dymax = 1.0f / ((b - a) + EPSV);
            g_min_key   = 0xFFFFFFFFu;
            g_tick      = 0;
            g_done      = 0;
        }
    }

    // ---------------- ticket barrier (release/acquire) ----------------
    __syncthreads();
    if (tid == 0) {
        __threadfence();
        int old = atomicAdd(&g_arrive, 1);
        int target = (old / GRID2 + 1) * GRID2;
        while (*(volatile int*)&g_arrive < target) { }
        __threadfence();
    }
    __syncthreads();

    // ---------------- phase 1: GEMM on 4 tiles ----------------
    int ts = blockIdx.x * 4;
    int te = ts + 4;

    int by = 0, off = 0;
    while (ts >= off + (NT - by)) { off += (NT - by); by++; }
    int bx = by + (ts - off);

    float mymin = 1e30f;
    int t = ts;
    while (t < te) {
        int nb = NT - bx;
        if (nb > te - t) nb = te - t;

        load_panel(sb, OFF_A, by, tid);
        load_panel(sb, OFF_B0, bx, tid);
        cp_commit();

        for (int j = 0; j < nb; j++) {
            uint32_t bOf = (j & 1) ? OFF_B1 : OFF_B0;
            if (j + 1 < nb) {
                load_panel(sb, (j & 1) ? OFF_B0 : OFF_B1, bx + j + 1, tid);
                cp_commit();
                cp_wait<1>();
            } else {
                cp_wait<0>();
            }
            __syncthreads();

            float c[2][4][4];
            tile_mma(sb, bOf, wm, wn, lane, c);

            float* dst = g_simu + (size_t)(t + j) * 16384;
            #pragma unroll
            for (int im = 0; im < 2; im++)
                #pragma unroll
                for (int in = 0; in < 4; in++) {
                    int rl = wm * 32 + im * 16 + tr;
                    int cl = wn * 32 + in * 8 + tq;
                    float2 v0 = make_float2(c[im][in][0], c[im][in][1]);
                    float2 v1 = make_float2(c[im][in][2], c[im][in][3]);
                    *(float2*)(dst + rl * 128 + cl)       = v0;
                    *(float2*)(dst + (rl + 8) * 128 + cl) = v1;
                    mymin = fminf(mymin, fminf(fminf(v0.x, v0.y), fminf(v1.x, v1.y)));
                }
            __syncthreads();
        }
        t += nb;
        bx += nb;
        if (bx >= NT) { by++; bx = by; }
    }

    #pragma unroll
    for (int o = 16; o; o >>= 1) mymin = fminf(mymin, __shfl_xor_sync(0xffffffffu, mymin, o));
    if (lane == 0) wmin[wid] = mymin;
    __syncthreads();
    if (tid == 0) {
        float m = wmin[0];
        #pragma unroll
        for (int w = 1; w < 16; w++) m = fminf(m, wmin[w]);
        atomicMin(&g_min_key, fflip(m));
    }
}

// ---------------- kernel 2: persistent work-stealing epilogue ---------------
__global__ void __launch_bounds__(512, 2) epiflat_kernel(const float* __restrict__ labels) {
    __shared__ float yr[128], yc[128];
    __shared__ float rowacc[3][4][128];
    __shared__ float colacc[16][3][128];
    __shared__ int s_t;
    int tid = threadIdx.x, w = tid >> 5, l = tid & 31;

    float inv_dz = 1.0f / ((1.0f - funflip(g_min_key)) + EPSV);
    float inv_dy = g_inv_dymax;
    const float K1 = INV_T * LOG2E;
    const float K2 = -2.0f * LOG2E;

    while (true) {
        if (tid == 0) s_t = atomicAdd(&g_tick, 1);
        __syncthreads();
        int t = s_t;
        if (t >= NTILES) return;

        int by = 0, off = 0;
        while (t >= off + (NT - by)) { off += (NT - by); by++; }
        int bx = by + (t - off);
        bool diag = (by == bx);

        for (int i = tid; i < 128; i += 512) {
            yr[i] = labels[(by * 128 + i) & (Bb - 1)];
            yc[i] = labels[(bx * 128 + i) & (Bb - 1)];
        }
        __syncthreads();

        const float4* tp = (const float4*)(g_simu + (size_t)t * 16384);
        float yj[4];
        #pragma unroll
        for (int e = 0; e < 4; e++) yj[e] = yc[4 * l + e];

        float cd[4] = {0,0,0,0}, c1v[4] = {0,0,0,0}, c2v[4] = {0,0,0,0};

        #pragma unroll
        for (int it = 0; it < 8; it++) {
            int row = it * 16 + w;
            float4 s4 = tp[row * 32 + l];
            float se[4] = {s4.x, s4.y, s4.z, s4.w};
            float yi = yr[row];
            float rd = 0.0f, r1 = 0.0f, r2 = 0.0f;

            if (!diag) {
                #pragma unroll
                for (int e = 0; e < 4; e++) {
                    float s   = se[e];
                    float es  = exp2f(s * K1);
                    float dy  = yi - yj[e];
                    float wk  = exp2f(dy * (dy * K2));
                    float u   = fmaf(-s, inv_dz, fmaf(-fabsf(dy), inv_dy, inv_dz));
                    float wh  = fmaf(wk, u, 1.0f + fmaxf(-u, 0.0f));
                    float wh2 = wh * wh;
                    rd += es; r1 += wh; r2 = fmaf(wh2, s, r2);
                    cd[e] += es; c1v[e] += wh; c2v[e] = fmaf(wh2, s, c2v[e]);
                }
            } else {
                #pragma unroll
                for (int e = 0; e < 4; e++) {
                    float s   = se[e];
                    float es  = exp2f(s * K1);
                    float dy  = yi - yj[e];
                    float wk  = exp2f(dy * (dy * K2));
                    float u   = fmaf(-s, inv_dz, fmaf(-fabsf(dy), inv_dy, inv_dz));
                    float wh  = fmaf(wk, u, 1.0f + fmaxf(-u, 0.0f));
                    if (row == 4 * l + e) { es = 0.0f; wh = 0.0f; }
                    float wh2 = wh * wh;
                    rd += es; r1 += wh; r2 = fmaf(wh2, s, r2);
                    cd[e] += es; c1v[e] += wh; c2v[e] = fmaf(wh2, s, c2v[e]);
                }
            }

            #pragma unroll
            for (int o = 1; o <= 4; o <<= 1) {
                rd += __shfl_xor_sync(0xffffffffu, rd, o);
                r1 += __shfl_xor_sync(0xffffffffu, r1, o);
                r2 += __shfl_xor_sync(0xffffffffu, r2, o);
            }
            if ((l & 7) == 0) {
                int g = l >> 3;
                rowacc[0][g][row] = rd;
                rowacc[1][g][row] = r1;
                rowacc[2][g][row] = r2;
            }
        }

        #pragma unroll
        for (int e = 0; e < 4; e++) {
            colacc[w][0][4 * l + e] = cd[e];
            colacc[w][1][4 * l + e] = c1v[e];
            colacc[w][2][4 * l + e] = c2v[e];
            cd[e] = 0.0f; c1v[e] = 0.0f; c2v[e] = 0.0f;
        }
        __syncthreads();

        if (tid < 128) {
            int row = tid, ig = by * 128 + row;
            #pragma unroll
            for (int k = 0; k < 3; k++)
                g_pdr[k][ig][bx] = (rowacc[k][0][row] + rowacc[k][1][row])
                                 + (rowacc[k][2][row] + rowacc[k][3][row]);
        } else if (tid < 256) {
            int col = tid - 128, jg = bx * 128 + col;
            #pragma unroll
            for (int k = 0; k < 3; k++) {
                float v = 0.0f;
                #pragma unroll
                for (int ww = 0; ww < 16; ww++) v += colacc[ww][k][col];
                g_pdc[k][jg][by] = diag ? 0.0f : v;
            }
        }
        __syncthreads();
    }
}

// ---------------- kernel 3: warp-per-row reduce + final mean ----------------
__global__ void __launch_bounds__(1024) rowfinal_kernel(float* __restrict__ out) {
    __shared__ float red[32];
    __shared__ float red2[4];
    __shared__ int s_last;
    int tid = threadIdx.x, w = tid >> 5, l = tid & 31;
    int i = blockIdx.x * 32 + w;       // row handled by this warp
    int p = i >> 7;

    float d = 0.0f, a = 0.0f, b = 0.0f;
    if (l >= p) {                      // row-side: tiles (p, l)
        d = g_pdr[0][i][l];
        a = g_pdr[1][i][l];
        b = g_pdr[2][i][l];
    }
    if (l <= p) {                      // col-side: tiles (l, p); diag slot holds 0
        d += g_pdc[0][i][l];
        a += g_pdc[1][i][l];
        b += g_pdc[2][i][l];
    }
    #pragma unroll
    for (int o = 16; o; o >>= 1) {
        d += __shfl_xor_sync(0xffffffffu, d, o);
        a += __shfl_xor_sync(0xffffffffu, a, o);
        b += __shfl_xor_sync(0xffffffffu, b, o);
    }

    if (l == 0) {
        b *= INV_T;
        float L = logf(d + EPSV);
        red[w] = (b - a * L) / (a + EPSV);
    }
    __syncthreads();

    if (tid == 0) {
        float s = 0.0f;
        #pragma unroll
        for (int x = 0; x < 32; x++) s += red[x];
        g_part[blockIdx.x] = s;
        __threadfence();
        int old = atomicAdd(&g_done, 1);
        s_last = (old == RGRID - 1);
    }
    __syncthreads();

    if (s_last) {
        if (tid < 128) {
            float v = *(volatile float*)&g_part[tid];
            #pragma unroll
            for (int o = 16; o; o >>= 1) v += __shfl_xor_sync(0xffffffffu, v, o);
            if (l == 0) red2[w] = v;
        }
        __syncthreads();
        if (tid == 0) {
            float tot = red2[0] + red2[1] + red2[2] + red2[3];
            out[0] = -(tot / (float)Nn);
        }
    }
}

// ---------------- launch ----------------
extern "C" void kernel_launch(void* const* d_in, const int* in_sizes, int n_in,
                              void* d_out, int out_size) {
    const float* feats  = (const float*)d_in[0];
    const float* labels = (const float*)d_in[1];
    float* out = (float*)d_out;

    cudaFuncSetAttribute(simgen_kernel, cudaFuncAttributeMaxDynamicSharedMemorySize, PANEL_BYTES);

    simgen_kernel<<<GRID2, 512, PANEL_BYTES>>>(feats, labels);
    epiflat_kernel<<<EGRID, 512>>>(labels);
    rowfinal_kernel<<<RGRID, 1024>>>(out);
}